// round 8
// baseline (speedup 1.0000x reference)
#include <cuda_runtime.h>
#include <cstdint>

// RandomPixelMapping: out[b,c,y,x] = table[b,c, clip(rint(x*255), 0, 255)]
// x: [64,3,512,512] f32, table: [64,3,256] f32, out: [64,3,512,512] f32.
// R8: single-wave launch (768 CTAs = 148 SMs x ~6 resident, zero wave
//     transitions), conflict-free bank-replicated LUT, 8-deep vec4 batches.

#define PLANE_ELEMS    (512 * 512)          // 262144 elems per (b,c) plane
#define VEC_PER_PLANE  (PLANE_ELEMS / 4)    // 65536 float4
#define THREADS        256
#define CHUNKS         4                    // blocks per plane -> 768 CTAs
#define VEC_PER_BLOCK  (VEC_PER_PLANE / CHUNKS)      // 16384 float4 per block
#define BATCH          8                                  // MLP per inner batch
#define NBATCH         (VEC_PER_BLOCK / (THREADS * BATCH))   // 8 outer iters

__global__ __launch_bounds__(THREADS)
void RandomPixelMapping_19593640805006_kernel(
    const float4* __restrict__ x,
    const float*  __restrict__ table,
    float4*       __restrict__ out)
{
    // Bank-replicated LUT: lut[idx][lane]; lane l always reads bank l.
    __shared__ float lut[256][32];

    const int tid   = threadIdx.x;
    const int lane  = tid & 31;
    const int plane = blockIdx.y;                 // 0..191  (b*3 + c)

    // Vectorized rotated fill: warp STS.128 hits 8 distinct bank quads.
    {
        const float t = table[plane * 256 + tid];
        const float4 tv = make_float4(t, t, t, t);
        float4* row = reinterpret_cast<float4*>(lut[tid]);
#pragma unroll
        for (int j = 0; j < 8; ++j)
            row[(j + lane) & 7] = tv;
    }
    __syncthreads();

    const size_t base = (size_t)plane * VEC_PER_PLANE
                      + (size_t)blockIdx.x * VEC_PER_BLOCK
                      + tid;

#pragma unroll
    for (int it = 0; it < NBATCH; ++it) {
        const size_t b0 = base + (size_t)it * (THREADS * BATCH);

        // Front-batch 8 independent vec4 loads (MLP=8).
        float4 v[BATCH];
#pragma unroll
        for (int j = 0; j < BATCH; ++j)
            v[j] = x[b0 + (size_t)j * THREADS];

#pragma unroll
        for (int j = 0; j < BATCH; ++j) {
            float4 r;
            int i0 = __float2int_rn(v[j].x * 255.0f);
            int i1 = __float2int_rn(v[j].y * 255.0f);
            int i2 = __float2int_rn(v[j].z * 255.0f);
            int i3 = __float2int_rn(v[j].w * 255.0f);
            i0 = min(max(i0, 0), 255);
            i1 = min(max(i1, 0), 255);
            i2 = min(max(i2, 0), 255);
            i3 = min(max(i3, 0), 255);
            r.x = lut[i0][lane];
            r.y = lut[i1][lane];
            r.z = lut[i2][lane];
            r.w = lut[i3][lane];
            out[b0 + (size_t)j * THREADS] = r;
        }
    }
}

extern "C" void kernel_launch(void* const* d_in, const int* in_sizes, int n_in,
                              void* d_out, int out_size)
{
    const float4* x     = (const float4*)d_in[0];
    const float*  table = (const float*) d_in[1];
    float4*       out   = (float4*)d_out;

    dim3 grid(CHUNKS, 64 * 3);   // 4 chunks x 192 planes = 768 CTAs (1 wave)
    RandomPixelMapping_19593640805006_kernel<<<grid, THREADS>>>(x, table, out);
}

// round 9
// speedup vs baseline: 1.0956x; 1.0956x over previous
#include <cuda_runtime.h>
#include <cstdint>

// RandomPixelMapping: out[b,c,y,x] = table[b,c, clip(rint(x*255), 0, 255)]
// x: [64,3,512,512] f32, table: [64,3,256] f32, out: [64,3,512,512] f32.
// R9 (final): R3 structure (conflict-free bank-replicated LUT, CHUNKS=32,
//   8-deep vec4 batches) + global loads issued BEFORE the LUT fill so the
//   fill+barrier drain under the first DRAM round-trip.

#define PLANE_ELEMS    (512 * 512)          // 262144 elems per (b,c) plane
#define VEC_PER_PLANE  (PLANE_ELEMS / 4)    // 65536 float4
#define THREADS        256
#define CHUNKS         32                   // blocks per plane
#define VEC_PER_BLOCK  (VEC_PER_PLANE / CHUNKS)      // 2048 float4 per block
#define VEC_PER_THREAD (VEC_PER_BLOCK / THREADS)     // 8 float4 per thread

__global__ __launch_bounds__(THREADS)
void RandomPixelMapping_19593640805006_kernel(
    const float4* __restrict__ x,
    const float*  __restrict__ table,
    float4*       __restrict__ out)
{
    // Bank-replicated LUT: lut[idx][lane]; lane l always reads bank l
    // -> zero-conflict gather regardless of index distribution.
    __shared__ float lut[256][32];

    const int tid   = threadIdx.x;
    const int lane  = tid & 31;
    const int plane = blockIdx.y;                 // 0..191  (b*3 + c)

    const size_t base = (size_t)plane * VEC_PER_PLANE
                      + (size_t)blockIdx.x * VEC_PER_BLOCK
                      + tid;

    // 1) Issue all 8 independent vec4 global loads FIRST (MLP=8).
    //    They have no smem dependence; their ~600-cycle DRAM latency
    //    hides the LUT fill and the barrier below.
    float4 v[VEC_PER_THREAD];
#pragma unroll
    for (int j = 0; j < VEC_PER_THREAD; ++j)
        v[j] = x[base + (size_t)j * THREADS];

    // 2) LUT fill while loads are in flight. Thread tid owns row tid;
    //    lane-rotated STS.128 groups -> minimum-phase (4) warp stores.
    {
        const float t = table[plane * 256 + tid];
        const float4 tv = make_float4(t, t, t, t);
        float4* row = reinterpret_cast<float4*>(lut[tid]);
#pragma unroll
        for (int j = 0; j < 8; ++j)
            row[(j + lane) & 7] = tv;
    }
    __syncthreads();

    // 3) Conflict-free gather + streaming store.
#pragma unroll
    for (int j = 0; j < VEC_PER_THREAD; ++j) {
        float4 r;
        int i0 = __float2int_rn(v[j].x * 255.0f);
        int i1 = __float2int_rn(v[j].y * 255.0f);
        int i2 = __float2int_rn(v[j].z * 255.0f);
        int i3 = __float2int_rn(v[j].w * 255.0f);
        i0 = min(max(i0, 0), 255);
        i1 = min(max(i1, 0), 255);
        i2 = min(max(i2, 0), 255);
        i3 = min(max(i3, 0), 255);
        r.x = lut[i0][lane];
        r.y = lut[i1][lane];
        r.z = lut[i2][lane];
        r.w = lut[i3][lane];
        out[base + (size_t)j * THREADS] = r;
    }
}

extern "C" void kernel_launch(void* const* d_in, const int* in_sizes, int n_in,
                              void* d_out, int out_size)
{
    const float4* x     = (const float4*)d_in[0];
    const float*  table = (const float*) d_in[1];
    float4*       out   = (float4*)d_out;

    dim3 grid(CHUNKS, 64 * 3);   // 32 chunks x 192 planes = 6144 CTAs
    RandomPixelMapping_19593640805006_kernel<<<grid, THREADS>>>(x, table, out);
}

// round 10
// speedup vs baseline: 1.0962x; 1.0005x over previous
#include <cuda_runtime.h>
#include <cstdint>

// RandomPixelMapping: out[b,c,y,x] = table[b,c, clip(rint(x*255), 0, 255)]
// x: [64,3,512,512] f32, table: [64,3,256] f32, out: [64,3,512,512] f32.
//
// FINAL (R3 config — best measured: 56.1us kernel, 7.2 TB/s app-level =
// ~90% of HBM spec, memory-controller roofline):
//  - bank-replicated LUT lut[idx][lane] (32 KB smem): lane l always reads
//    bank l -> provably conflict-free gather for any index distribution
//  - lane-rotated STS.128 fill (minimum-phase warp stores)
//  - 8-deep front-batched vec4 loads (MLP=8), CHUNKS=32 -> 6144 CTAs
//    (multi-wave oversubscription smooths per-CTA finish-time spread)
//  - __float2int_rn = round-to-nearest-even, matching jnp.round exactly

#define PLANE_ELEMS    (512 * 512)          // 262144 elems per (b,c) plane
#define VEC_PER_PLANE  (PLANE_ELEMS / 4)    // 65536 float4
#define THREADS        256
#define CHUNKS         32                   // blocks per plane
#define VEC_PER_BLOCK  (VEC_PER_PLANE / CHUNKS)      // 2048 float4 per block
#define VEC_PER_THREAD (VEC_PER_BLOCK / THREADS)     // 8 float4 per thread

__global__ __launch_bounds__(THREADS)
void RandomPixelMapping_19593640805006_kernel(
    const float4* __restrict__ x,
    const float*  __restrict__ table,
    float4*       __restrict__ out)
{
    __shared__ float lut[256][32];

    const int tid   = threadIdx.x;
    const int lane  = tid & 31;
    const int plane = blockIdx.y;                 // 0..191  (b*3 + c)

    // Fill: thread tid owns LUT row tid; rotate the float4 column-group by
    // lane so each warp's STS.128 completes in the 4-phase minimum.
    {
        const float t = table[plane * 256 + tid];
        const float4 tv = make_float4(t, t, t, t);
        float4* row = reinterpret_cast<float4*>(lut[tid]);
#pragma unroll
        for (int j = 0; j < 8; ++j)
            row[(j + lane) & 7] = tv;
    }
    __syncthreads();

    const size_t base = (size_t)plane * VEC_PER_PLANE
                      + (size_t)blockIdx.x * VEC_PER_BLOCK
                      + tid;

    // Front-batch 8 independent vec4 loads (MLP=8), then conflict-free
    // gather and coalesced vec4 stores.
    float4 v[VEC_PER_THREAD];
#pragma unroll
    for (int j = 0; j < VEC_PER_THREAD; ++j)
        v[j] = x[base + (size_t)j * THREADS];

#pragma unroll
    for (int j = 0; j < VEC_PER_THREAD; ++j) {
        float4 r;
        int i0 = __float2int_rn(v[j].x * 255.0f);
        int i1 = __float2int_rn(v[j].y * 255.0f);
        int i2 = __float2int_rn(v[j].z * 255.0f);
        int i3 = __float2int_rn(v[j].w * 255.0f);
        i0 = min(max(i0, 0), 255);
        i1 = min(max(i1, 0), 255);
        i2 = min(max(i2, 0), 255);
        i3 = min(max(i3, 0), 255);
        r.x = lut[i0][lane];
        r.y = lut[i1][lane];
        r.z = lut[i2][lane];
        r.w = lut[i3][lane];
        out[base + (size_t)j * THREADS] = r;
    }
}

extern "C" void kernel_launch(void* const* d_in, const int* in_sizes, int n_in,
                              void* d_out, int out_size)
{
    const float4* x     = (const float4*)d_in[0];
    const float*  table = (const float*) d_in[1];
    float4*       out   = (float4*)d_out;

    dim3 grid(CHUNKS, 64 * 3);   // 32 chunks x 192 planes = 6144 CTAs
    RandomPixelMapping_19593640805006_kernel<<<grid, THREADS>>>(x, table, out);
}

// round 11
// speedup vs baseline: 1.0967x; 1.0005x over previous
#include <cuda_runtime.h>
#include <cstdint>

// RandomPixelMapping: out[b,c,y,x] = table[b,c, clip(rint(x*255), 0, 255)]
// x: [64,3,512,512] f32, table: [64,3,256] f32, out: [64,3,512,512] f32.
//
// FINAL — memory-controller roofline reached:
//   best kernel 55.4us, 6278 GB/s ncu / 7.28 TB/s app-level (91% of HBM spec).
// Design:
//  - bank-replicated LUT lut[idx][lane] (32 KB smem): lane l always reads
//    bank l -> provably conflict-free gather for any index distribution
//    (the single measured win: -2.2us vs scalar LUT)
//  - lane-rotated STS.128 fill (minimum-phase warp stores)
//  - 8-deep front-batched vec4 loads (MLP=8), CHUNKS=32 -> 6144 CTAs
//    (multi-wave oversubscription backfills per-CTA finish-time spread;
//     single-wave launch measured -6% regression)
//  - __float2int_rn = round-to-nearest-even, matching jnp.round exactly
// Falsified axes (all neutral): MLP depth, .cs / evict_last+first hints,
// 256-bit ld/st.v8.b32, fill amortization, load-before-fill overlap.

#define PLANE_ELEMS    (512 * 512)          // 262144 elems per (b,c) plane
#define VEC_PER_PLANE  (PLANE_ELEMS / 4)    // 65536 float4
#define THREADS        256
#define CHUNKS         32                   // blocks per plane
#define VEC_PER_BLOCK  (VEC_PER_PLANE / CHUNKS)      // 2048 float4 per block
#define VEC_PER_THREAD (VEC_PER_BLOCK / THREADS)     // 8 float4 per thread

__global__ __launch_bounds__(THREADS)
void RandomPixelMapping_19593640805006_kernel(
    const float4* __restrict__ x,
    const float*  __restrict__ table,
    float4*       __restrict__ out)
{
    __shared__ float lut[256][32];

    const int tid   = threadIdx.x;
    const int lane  = tid & 31;
    const int plane = blockIdx.y;                 // 0..191  (b*3 + c)

    // Fill: thread tid owns LUT row tid; rotate the float4 column-group by
    // lane so each warp's STS.128 completes in the 4-phase minimum.
    {
        const float t = table[plane * 256 + tid];
        const float4 tv = make_float4(t, t, t, t);
        float4* row = reinterpret_cast<float4*>(lut[tid]);
#pragma unroll
        for (int j = 0; j < 8; ++j)
            row[(j + lane) & 7] = tv;
    }
    __syncthreads();

    const size_t base = (size_t)plane * VEC_PER_PLANE
                      + (size_t)blockIdx.x * VEC_PER_BLOCK
                      + tid;

    // Front-batch 8 independent vec4 loads (MLP=8), then conflict-free
    // gather and coalesced vec4 stores.
    float4 v[VEC_PER_THREAD];
#pragma unroll
    for (int j = 0; j < VEC_PER_THREAD; ++j)
        v[j] = x[base + (size_t)j * THREADS];

#pragma unroll
    for (int j = 0; j < VEC_PER_THREAD; ++j) {
        float4 r;
        int i0 = __float2int_rn(v[j].x * 255.0f);
        int i1 = __float2int_rn(v[j].y * 255.0f);
        int i2 = __float2int_rn(v[j].z * 255.0f);
        int i3 = __float2int_rn(v[j].w * 255.0f);
        i0 = min(max(i0, 0), 255);
        i1 = min(max(i1, 0), 255);
        i2 = min(max(i2, 0), 255);
        i3 = min(max(i3, 0), 255);
        r.x = lut[i0][lane];
        r.y = lut[i1][lane];
        r.z = lut[i2][lane];
        r.w = lut[i3][lane];
        out[base + (size_t)j * THREADS] = r;
    }
}

extern "C" void kernel_launch(void* const* d_in, const int* in_sizes, int n_in,
                              void* d_out, int out_size)
{
    const float4* x     = (const float4*)d_in[0];
    const float*  table = (const float*) d_in[1];
    float4*       out   = (float4*)d_out;

    dim3 grid(CHUNKS, 64 * 3);   // 32 chunks x 192 planes = 6144 CTAs
    RandomPixelMapping_19593640805006_kernel<<<grid, THREADS>>>(x, table, out);
}